// round 5
// baseline (speedup 1.0000x reference)
#include <cuda_runtime.h>
#include <cstdint>
#include <cstddef>

// ---------------------------------------------------------------------------
// ModularTreeMLPPredictor: D=11 level-sequential tree MLP.
//   level l (l = D-1 .. 0): n = 2^l nodes, start = n-1
//   x = [features(32) | left | right | treatment]  (K1 = 35)
//   h  = relu(x  @ W1[l] + b1[l])   (35 -> 64)
//   h2 = relu(h  @ W2[l] + b2[l])   (64 -> 64)
//   y  =       h2 @ W3[l] + b3[l]   (64 -> 1)
//   out[:, start:start+n] = y ;  children of level l read outputs of l+1.
//
// Levels 10..6: one fused kernel per level (chip-filling grids).
// Levels 5..0:  ONE kernel, 512 blocks; block b walks its own subtree
//               (recursion is per-batch-element independent below the
//               chip-filling levels), children kept in smem ybuf.
// Weights in smem; activations staged TRANSPOSED ([k][row], STRIDE=TM+2)
// so row-pairs load as packed f32x2 operands for fma.rn.f32x2 (FFMA2 =
// 2x fp32 FMA rate on sm_103a; PTX-only, never auto-fused by ptxas).
// STRIDE == 2 mod 8: 4-way (not 8-way) conflicts on column-strided STS.64.
// ---------------------------------------------------------------------------

#define DLEV   11
#define BATCH  512
#define NNODES 2047
#define FDIM   32
#define HDIM   64
#define K1     35

typedef unsigned long long u64;

__device__ __forceinline__ u64 dup_f(float x) {
    u64 r;
    asm("mov.b64 %0, {%1, %1};" : "=l"(r) : "r"(__float_as_uint(x)));
    return r;
}
__device__ __forceinline__ void ffma2(u64 &d, u64 a, u64 b) {
    asm("fma.rn.f32x2 %0, %1, %2, %0;" : "+l"(d) : "l"(a), "l"(b));
}
__device__ __forceinline__ u64 relu2(u64 v) {
    float lo = __uint_as_float((unsigned)(v & 0xffffffffull));
    float hi = __uint_as_float((unsigned)(v >> 32));
    lo = fmaxf(lo, 0.f);
    hi = fmaxf(hi, 0.f);
    return ((u64)__float_as_uint(hi) << 32) | (u64)__float_as_uint(lo);
}

// smem float layout (dynamic):
//   W1s[2240] | b1s[64] | W2s[4096] | b2s[64] | W3s[64] | b3s[8]
//   bufA[HDIM*STRIDE] | bufB[HDIM*STRIDE] | (tail only) ybuf[66]
#define WOFF (K1*HDIM + HDIM + HDIM*HDIM + HDIM + HDIM + 8)  // 6536 floats

// ---- shared compute engine: 3-layer MLP on a TM-row transposed tile ----
// Requires x staged in bufA[k][r] (k = 0..K1-1). Leaves h2 in bufA.
// Caller provides r0/c0 thread mapping. Writes y for rows < nvalid via
// the store callback encoded here as direct out/ybuf pointers.
template <int TM>
__device__ __forceinline__ void mlp_layers12(float* bufA, float* bufB,
                                             const float* W1s, const float* b1s,
                                             const float* W2s, const float* b2s,
                                             int r0, int c0)
{
    constexpr int STRIDE = TM + 2;
    constexpr int PAIRS  = TM / 32;

    // layer 1: bufA(x) -> bufB(h)
    {
        u64 acc[PAIRS][4];
        #pragma unroll
        for (int j = 0; j < 4; j++) {
            u64 bb = dup_f(b1s[c0 + j]);
            #pragma unroll
            for (int p = 0; p < PAIRS; p++) acc[p][j] = bb;
        }
        #pragma unroll 7
        for (int k = 0; k < K1; k++) {
            const u64* arow = (const u64*)(bufA + k * STRIDE + r0);
            u64 a[PAIRS];
            #pragma unroll
            for (int p = 0; p < PAIRS; p++) a[p] = arow[p];
            float4 w4 = *(const float4*)(W1s + k * HDIM + c0);
            u64 bj0 = dup_f(w4.x), bj1 = dup_f(w4.y);
            u64 bj2 = dup_f(w4.z), bj3 = dup_f(w4.w);
            #pragma unroll
            for (int p = 0; p < PAIRS; p++) {
                ffma2(acc[p][0], a[p], bj0);
                ffma2(acc[p][1], a[p], bj1);
                ffma2(acc[p][2], a[p], bj2);
                ffma2(acc[p][3], a[p], bj3);
            }
        }
        #pragma unroll
        for (int j = 0; j < 4; j++)
            #pragma unroll
            for (int p = 0; p < PAIRS; p++)
                *(u64*)(bufB + (c0 + j) * STRIDE + r0 + 2 * p) = relu2(acc[p][j]);
    }
    __syncthreads();

    // layer 2: bufB(h) -> bufA(h2)
    {
        u64 acc[PAIRS][4];
        #pragma unroll
        for (int j = 0; j < 4; j++) {
            u64 bb = dup_f(b2s[c0 + j]);
            #pragma unroll
            for (int p = 0; p < PAIRS; p++) acc[p][j] = bb;
        }
        #pragma unroll 8
        for (int k = 0; k < HDIM; k++) {
            const u64* arow = (const u64*)(bufB + k * STRIDE + r0);
            u64 a[PAIRS];
            #pragma unroll
            for (int p = 0; p < PAIRS; p++) a[p] = arow[p];
            float4 w4 = *(const float4*)(W2s + k * HDIM + c0);
            u64 bj0 = dup_f(w4.x), bj1 = dup_f(w4.y);
            u64 bj2 = dup_f(w4.z), bj3 = dup_f(w4.w);
            #pragma unroll
            for (int p = 0; p < PAIRS; p++) {
                ffma2(acc[p][0], a[p], bj0);
                ffma2(acc[p][1], a[p], bj1);
                ffma2(acc[p][2], a[p], bj2);
                ffma2(acc[p][3], a[p], bj3);
            }
        }
        #pragma unroll
        for (int j = 0; j < 4; j++)
            #pragma unroll
            for (int p = 0; p < PAIRS; p++)
                *(u64*)(bufA + (c0 + j) * STRIDE + r0 + 2 * p) = relu2(acc[p][j]);
    }
    __syncthreads();
}

// layer 3 dot: thread-split (row = tid>>1, half = tid&1), shfl-combined.
template <int TM>
__device__ __forceinline__ float mlp_layer3(const float* bufA, const float* W3s,
                                            int tid)
{
    constexpr int STRIDE = TM + 2;
    const int row  = tid >> 1;
    const int half = tid & 1;
    float y = 0.f;
    if (row < TM) {
        const float* col = bufA + half * 32 * STRIDE + row;
        const float* w   = W3s + half * 32;
        #pragma unroll 8
        for (int c = 0; c < 32; c++)
            y = fmaf(col[c * STRIDE], w[c], y);
    }
    y += __shfl_xor_sync(0xffffffffu, y, 1);
    return y;   // valid for half==0, row<TM
}

// ---------------- big levels (l >= 6): one launch per level ----------------
template <int TM>
__global__ void __launch_bounds__(256, 2)
level_kernel(const float* __restrict__ features,
             const float* __restrict__ treatment,
             float* __restrict__ out,
             const float* __restrict__ W1, const float* __restrict__ b1,
             const float* __restrict__ W2, const float* __restrict__ b2,
             const float* __restrict__ W3, const float* __restrict__ b3,
             int lshift, int leaf)
{
    constexpr int STRIDE = TM + 2;
    const int n     = 1 << lshift;
    const int start = n - 1;

    extern __shared__ float sm[];
    float* W1s  = sm;
    float* b1s  = W1s + K1 * HDIM;
    float* W2s  = b1s + HDIM;
    float* b2s  = W2s + HDIM * HDIM;
    float* W3s  = b2s + HDIM;
    float* b3s  = W3s + HDIM;
    float* bufA = sm + WOFF;
    float* bufB = bufA + HDIM * STRIDE;

    const int tid = threadIdx.x;

    for (int i = tid; i < K1 * HDIM; i += 256)   W1s[i] = W1[i];
    for (int i = tid; i < HDIM * HDIM; i += 256) W2s[i] = W2[i];
    if (tid < HDIM) {
        b1s[tid] = b1[tid];
        b2s[tid] = b2[tid];
        W3s[tid] = W3[tid];
    }
    if (tid == 0) b3s[0] = b3[0];

    const int row0 = blockIdx.x * TM;
    for (int i = tid; i < TM * (FDIM / 4); i += 256) {
        int r = i >> 3;
        int q = i & 7;
        int g = row0 + r;
        int b = g >> lshift;
        int node = g & (n - 1);
        float4 v = *(const float4*)
            (features + ((size_t)b * NNODES + start + node) * FDIM + 4 * q);
        bufA[(4 * q + 0) * STRIDE + r] = v.x;
        bufA[(4 * q + 1) * STRIDE + r] = v.y;
        bufA[(4 * q + 2) * STRIDE + r] = v.z;
        bufA[(4 * q + 3) * STRIDE + r] = v.w;
    }
    if (tid < TM) {
        int g = row0 + tid;
        int b = g >> lshift;
        int node = g & (n - 1);
        float lv = 0.f, rv = 0.f;
        if (!leaf) {
            const float* c = out + (size_t)b * NNODES + (2 * n - 1) + 2 * node;
            lv = c[0];
            rv = c[1];
        }
        bufA[32 * STRIDE + tid] = lv;
        bufA[33 * STRIDE + tid] = rv;
        bufA[34 * STRIDE + tid] = treatment[b];
    }
    __syncthreads();

    const int r0 = (tid >> 4) * (TM / 16);
    const int c0 = (tid & 15) * 4;
    mlp_layers12<TM>(bufA, bufB, W1s, b1s, W2s, b2s, r0, c0);

    float y = mlp_layer3<TM>(bufA, W3s, tid);
    const int row = tid >> 1;
    if ((tid & 1) == 0 && row < TM) {
        int g = row0 + row;
        int b = g >> lshift;
        int node = g & (n - 1);
        out[(size_t)b * NNODES + start + node] = y + b3s[0];
    }
}

// ------------- tail levels (l = 5..0): one launch, 512 blocks -------------
__global__ void __launch_bounds__(256, 2)
tail_kernel(const float* __restrict__ features,
            const float* __restrict__ treatment,
            float* __restrict__ out,
            const float* __restrict__ W1, const float* __restrict__ b1,
            const float* __restrict__ W2, const float* __restrict__ b2,
            const float* __restrict__ W3, const float* __restrict__ b3)
{
    constexpr int TM     = 32;
    constexpr int STRIDE = TM + 2;

    extern __shared__ float sm[];
    float* W1s  = sm;
    float* b1s  = W1s + K1 * HDIM;
    float* W2s  = b1s + HDIM;
    float* b2s  = W2s + HDIM * HDIM;
    float* W3s  = b2s + HDIM;
    float* b3s  = W3s + HDIM;
    float* bufA = sm + WOFF;
    float* bufB = bufA + HDIM * STRIDE;
    float* ybuf = bufB + HDIM * STRIDE;   // 64+2 floats: child values

    const int tid = threadIdx.x;
    const int b   = blockIdx.x;
    const float tval = treatment[b];

    // preload level-6 outputs (children of level 5): out[b*2047 + 63 .. +127)
    if (tid < 64)
        ybuf[tid] = out[(size_t)b * NNODES + 63 + tid];

    const int r0 = (tid >> 4) * (TM / 16);   // 2 rows/thread
    const int c0 = (tid & 15) * 4;

    for (int l = 5; l >= 0; --l) {
        const int n     = 1 << l;
        const int start = n - 1;
        const float* w1l = W1 + (size_t)l * K1 * HDIM;
        const float* b1l = b1 + (size_t)l * HDIM;
        const float* w2l = W2 + (size_t)l * HDIM * HDIM;
        const float* b2l = b2 + (size_t)l * HDIM;
        const float* w3l = W3 + (size_t)l * HDIM;
        const float* b3l = b3 + (size_t)l;

        __syncthreads();   // prior level fully done (ybuf, weight reads)

        // stage weights for this level
        for (int i = tid; i < K1 * HDIM; i += 256)   W1s[i] = w1l[i];
        for (int i = tid; i < HDIM * HDIM; i += 256) W2s[i] = w2l[i];
        if (tid < HDIM) {
            b1s[tid] = b1l[tid];
            b2s[tid] = b2l[tid];
            W3s[tid] = w3l[tid];
        }
        if (tid == 0) b3s[0] = b3l[0];

        // stage x for rows < n (rows >= n left stale; never stored)
        for (int i = tid; i < n * (FDIM / 4); i += 256) {
            int r = i >> 3;
            int q = i & 7;
            float4 v = *(const float4*)
                (features + ((size_t)b * NNODES + start + r) * FDIM + 4 * q);
            bufA[(4 * q + 0) * STRIDE + r] = v.x;
            bufA[(4 * q + 1) * STRIDE + r] = v.y;
            bufA[(4 * q + 2) * STRIDE + r] = v.z;
            bufA[(4 * q + 3) * STRIDE + r] = v.w;
        }
        if (tid < n) {
            bufA[32 * STRIDE + tid] = ybuf[2 * tid];
            bufA[33 * STRIDE + tid] = ybuf[2 * tid + 1];
            bufA[34 * STRIDE + tid] = tval;
        }
        __syncthreads();

        mlp_layers12<TM>(bufA, bufB, W1s, b1s, W2s, b2s, r0, c0);

        float y = mlp_layer3<TM>(bufA, W3s, tid);
        const int row = tid >> 1;
        if ((tid & 1) == 0 && row < n) {
            float yo = y + b3s[0];
            ybuf[row] = yo;
            out[(size_t)b * NNODES + start + row] = yo;
        }
    }
}

extern "C" void kernel_launch(void* const* d_in, const int* in_sizes, int n_in,
                              void* d_out, int out_size)
{
    const float* features  = (const float*)d_in[0];
    const float* treatment = (const float*)d_in[1];
    const float* W1 = (const float*)d_in[2];
    const float* b1 = (const float*)d_in[3];
    const float* W2 = (const float*)d_in[4];
    const float* b2 = (const float*)d_in[5];
    const float* W3 = (const float*)d_in[6];
    const float* b3 = (const float*)d_in[7];
    float* out = (float*)d_out;

    const int smem128 = (WOFF + 2 * HDIM * (128 + 2)) * 4;        // 92,704 B
    const int smemTail = (WOFF + 2 * HDIM * (32 + 2) + 66) * 4;   // 43,816 B
    cudaFuncSetAttribute(level_kernel<128>,
                         cudaFuncAttributeMaxDynamicSharedMemorySize, smem128);
    cudaFuncSetAttribute(tail_kernel,
                         cudaFuncAttributeMaxDynamicSharedMemorySize, smemTail);

    // big levels: 10..6, one launch each (chip-filling grids)
    for (int l = DLEV - 1; l >= 6; --l) {
        const int rows = BATCH << l;
        const int leaf = (l == DLEV - 1) ? 1 : 0;
        level_kernel<128><<<rows / 128, 256, smem128>>>(
            features, treatment, out,
            W1 + (size_t)l * K1 * HDIM, b1 + (size_t)l * HDIM,
            W2 + (size_t)l * HDIM * HDIM, b2 + (size_t)l * HDIM,
            W3 + (size_t)l * HDIM, b3 + (size_t)l,
            l, leaf);
    }
    // tail levels 5..0: one launch, block b = batch element b
    tail_kernel<<<BATCH, 256, smemTail>>>(
        features, treatment, out, W1, b1, W2, b2, W3, b3);
}